// round 3
// baseline (speedup 1.0000x reference)
#include <cuda_runtime.h>
#include <math.h>

// ---------------- problem constants (fixed shapes) ----------------
#define NNODES 50000
#define NEDGES 800000
#define IN_CH  256
#define HID    64
#define HEADS  2
#define C1     (HEADS * HID)        // 128
#define EE     (NEDGES + NNODES)    // 850000 edges incl. self loops
#define NEG_SLOPE 0.2f
#define BN_EPS    1e-5f
#define ENC_NEG_INF 0x807FFFFF      // encoded(-inf) for float atomicMax-as-int

// ---------------- scratch (device globals; no allocations) ----------------
__device__ float g_xl1[NNODES * C1];
__device__ float g_xr1[NNODES * C1];
__device__ float g_out1[NNODES * C1];      // agg accum -> h1 (in place)
__device__ float g_xl2[NNODES * HID];
__device__ float g_xr2[NNODES * HID];
__device__ float g_out2[NNODES * HID];     // agg accum -> h2 (in place)
__device__ float g_logits[EE * HEADS];
__device__ int   g_m1[NNODES * HEADS];
__device__ float g_s1[NNODES * HEADS];
__device__ int   g_m2[NNODES];
__device__ float g_s2[NNODES];

// monotonic float<->int encoding for atomicMax on signed int
__device__ __forceinline__ int   enc_f(float f) { int i = __float_as_int(f); return i >= 0 ? i : i ^ 0x7FFFFFFF; }
__device__ __forceinline__ float dec_i(int i)   { return __int_as_float(i >= 0 ? i : i ^ 0x7FFFFFFF); }

// ---------------- init ----------------
__global__ void init_kernel() {
    int i = blockIdx.x * blockDim.x + threadIdx.x;
    int stride = gridDim.x * blockDim.x;
    for (int j = i; j < NNODES * C1; j += stride) g_out1[j] = 0.f;
    for (int j = i; j < NNODES * HID; j += stride) g_out2[j] = 0.f;
    for (int j = i; j < NNODES * HEADS; j += stride) { g_s1[j] = 0.f; g_m1[j] = ENC_NEG_INF; }
    for (int j = i; j < NNODES; j += stride) { g_s2[j] = 0.f; g_m2[j] = ENC_NEG_INF; }
}

// ---------------- tiled SGEMM with bias: C[M,N] = A[M,K]@B[K,N] + bias ----------------
// scratch-id indirection (host code cannot take addresses of __device__ globals)
__device__ __forceinline__ float* scr(int id) {
    switch (id) {
        case 0: return g_xl1;
        case 1: return g_xr1;
        case 2: return g_out1;
        case 3: return g_xl2;
        case 4: return g_xr2;
        case 5: return g_out2;
    }
    return nullptr;
}

__global__ void sgemm_bias(const float* __restrict__ Aext, int aId,
                           const float* __restrict__ B,
                           const float* __restrict__ bias,
                           int cId, int M, int K, int N) {
    const float* A = (aId >= 0) ? scr(aId) : Aext;
    float* C = scr(cId);

    __shared__ float As[16][64];   // [k][row]
    __shared__ float Bs[16][64];   // [k][col]

    int tid = threadIdx.x;                // 256 threads
    int tx = tid % 16, ty = tid / 16;     // 16x16 thread tile, each does 4x4
    int rowBase = blockIdx.y * 64;
    int colBase = blockIdx.x * 64;

    float acc[4][4] = {};
    for (int k0 = 0; k0 < K; k0 += 16) {
        #pragma unroll
        for (int i = 0; i < 4; i++) {
            int lin = tid + i * 256;          // 0..1023
            int r  = lin >> 4, kk = lin & 15; // A tile 64x16
            int grow = rowBase + r;
            As[kk][r] = (grow < M) ? A[(size_t)grow * K + k0 + kk] : 0.f;
            int kb = lin >> 6, cb = lin & 63; // B tile 16x64
            int gcol = colBase + cb;
            Bs[kb][cb] = (gcol < N) ? B[(size_t)(k0 + kb) * N + gcol] : 0.f;
        }
        __syncthreads();
        #pragma unroll
        for (int kk = 0; kk < 16; kk++) {
            float ra[4], rb[4];
            #pragma unroll
            for (int i = 0; i < 4; i++) ra[i] = As[kk][ty * 4 + i];
            #pragma unroll
            for (int j = 0; j < 4; j++) rb[j] = Bs[kk][tx * 4 + j];
            #pragma unroll
            for (int i = 0; i < 4; i++)
                #pragma unroll
                for (int j = 0; j < 4; j++) acc[i][j] += ra[i] * rb[j];
        }
        __syncthreads();
    }
    #pragma unroll
    for (int i = 0; i < 4; i++) {
        int grow = rowBase + ty * 4 + i;
        if (grow >= M) continue;
        #pragma unroll
        for (int j = 0; j < 4; j++) {
            int gcol = colBase + tx * 4 + j;
            if (gcol < N) C[(size_t)grow * N + gcol] = acc[i][j] + bias[gcol];
        }
    }
}

// ---------------- edge helpers ----------------
__device__ __forceinline__ void edge_sd(int e, const int* __restrict__ esrc,
                                        const int* __restrict__ edst, int ne,
                                        int& s, int& d) {
    if (e < ne) { s = esrc[e]; d = edst[e]; }
    else        { s = e - ne; d = s; }       // self loop
}

// ---------------- layer 1: logits + segment max (warp per edge, 128 ch, 2 heads) ----
__global__ void gat1_logits(const int* __restrict__ esrc, const int* __restrict__ edst,
                            int ne, int ee, const float* __restrict__ att) {
    int warp = (blockIdx.x * blockDim.x + threadIdx.x) >> 5;
    int lane = threadIdx.x & 31;
    if (warp >= ee) return;
    int s, d; edge_sd(warp, esrc, edst, ne, s, d);

    const float* pl = g_xl1 + (size_t)s * C1;
    const float* pr = g_xr1 + (size_t)d * C1;
    float p0 = 0.f, p1 = 0.f;
    {
        float v;
        v = pl[lane]      + pr[lane];      v = v > 0.f ? v : NEG_SLOPE * v; p0 += att[lane]      * v;
        v = pl[lane + 32] + pr[lane + 32]; v = v > 0.f ? v : NEG_SLOPE * v; p0 += att[lane + 32] * v;
        v = pl[lane + 64] + pr[lane + 64]; v = v > 0.f ? v : NEG_SLOPE * v; p1 += att[lane + 64] * v;
        v = pl[lane + 96] + pr[lane + 96]; v = v > 0.f ? v : NEG_SLOPE * v; p1 += att[lane + 96] * v;
    }
    #pragma unroll
    for (int o = 16; o; o >>= 1) {
        p0 += __shfl_xor_sync(0xFFFFFFFFu, p0, o);
        p1 += __shfl_xor_sync(0xFFFFFFFFu, p1, o);
    }
    if (lane == 0) {
        g_logits[(size_t)warp * 2]     = p0;
        g_logits[(size_t)warp * 2 + 1] = p1;
        atomicMax(&g_m1[d * 2],     enc_f(p0));
        atomicMax(&g_m1[d * 2 + 1], enc_f(p1));
    }
}

// ---------------- layer 1: exp, segment sum, unnormalized aggregation ----------------
__global__ void gat1_agg(const int* __restrict__ esrc, const int* __restrict__ edst,
                         int ne, int ee) {
    int warp = (blockIdx.x * blockDim.x + threadIdx.x) >> 5;
    int lane = threadIdx.x & 31;
    if (warp >= ee) return;
    int s, d; edge_sd(warp, esrc, edst, ne, s, d);

    float l0 = g_logits[(size_t)warp * 2];
    float l1 = g_logits[(size_t)warp * 2 + 1];
    float p0 = __expf(l0 - dec_i(g_m1[d * 2]));
    float p1 = __expf(l1 - dec_i(g_m1[d * 2 + 1]));
    if (lane == 0) {
        atomicAdd(&g_s1[d * 2],     p0);
        atomicAdd(&g_s1[d * 2 + 1], p1);
    }
    const float* pl = g_xl1 + (size_t)s * C1;
    float* po = g_out1 + (size_t)d * C1;
    atomicAdd(&po[lane],      p0 * pl[lane]);
    atomicAdd(&po[lane + 32], p0 * pl[lane + 32]);
    atomicAdd(&po[lane + 64], p1 * pl[lane + 64]);
    atomicAdd(&po[lane + 96], p1 * pl[lane + 96]);
}

// ---------------- layer 1 finalize: normalize + bias + BN + ELU (in place) ----------------
__global__ void finalize1(const float* __restrict__ bias,
                          const float* __restrict__ g, const float* __restrict__ b,
                          const float* __restrict__ mean, const float* __restrict__ var) {
    int i = blockIdx.x * blockDim.x + threadIdx.x;
    if (i >= NNODES * C1) return;
    int node = i / C1, c = i % C1, h = c >> 6;
    float v = g_out1[i] / g_s1[node * 2 + h] + bias[c];
    v = (v - mean[c]) * rsqrtf(var[c] + BN_EPS) * g[c] + b[c];
    g_out1[i] = v > 0.f ? v : __expf(v) - 1.f;   // ELU
}

// ---------------- layer 2: logits (64 ch, 1 head) ----------------
__global__ void gat2_logits(const int* __restrict__ esrc, const int* __restrict__ edst,
                            int ne, int ee, const float* __restrict__ att) {
    int warp = (blockIdx.x * blockDim.x + threadIdx.x) >> 5;
    int lane = threadIdx.x & 31;
    if (warp >= ee) return;
    int s, d; edge_sd(warp, esrc, edst, ne, s, d);

    const float* pl = g_xl2 + (size_t)s * HID;
    const float* pr = g_xr2 + (size_t)d * HID;
    float p = 0.f, v;
    v = pl[lane]      + pr[lane];      v = v > 0.f ? v : NEG_SLOPE * v; p += att[lane]      * v;
    v = pl[lane + 32] + pr[lane + 32]; v = v > 0.f ? v : NEG_SLOPE * v; p += att[lane + 32] * v;
    #pragma unroll
    for (int o = 16; o; o >>= 1) p += __shfl_xor_sync(0xFFFFFFFFu, p, o);
    if (lane == 0) {
        g_logits[warp] = p;
        atomicMax(&g_m2[d], enc_f(p));
    }
}

__global__ void gat2_agg(const int* __restrict__ esrc, const int* __restrict__ edst,
                         int ne, int ee) {
    int warp = (blockIdx.x * blockDim.x + threadIdx.x) >> 5;
    int lane = threadIdx.x & 31;
    if (warp >= ee) return;
    int s, d; edge_sd(warp, esrc, edst, ne, s, d);

    float p = __expf(g_logits[warp] - dec_i(g_m2[d]));
    if (lane == 0) atomicAdd(&g_s2[d], p);
    const float* pl = g_xl2 + (size_t)s * HID;
    float* po = g_out2 + (size_t)d * HID;
    atomicAdd(&po[lane],      p * pl[lane]);
    atomicAdd(&po[lane + 32], p * pl[lane + 32]);
}

__global__ void finalize2(const float* __restrict__ bias,
                          const float* __restrict__ g, const float* __restrict__ b,
                          const float* __restrict__ mean, const float* __restrict__ var) {
    int i = blockIdx.x * blockDim.x + threadIdx.x;
    if (i >= NNODES * HID) return;
    int node = i / HID, c = i % HID;
    float v = g_out2[i] / g_s2[node] + bias[c];
    v = (v - mean[c]) * rsqrtf(var[c] + BN_EPS) * g[c] + b[c];
    g_out2[i] = v > 0.f ? v : __expf(v) - 1.f;
}

// ---------------- classifier: sigmoid(h2 @ Wc + bc), warp per node ----------------
__global__ void classifier(const float* __restrict__ Wc, const float* __restrict__ bc,
                           float* __restrict__ out) {
    int warp = (blockIdx.x * blockDim.x + threadIdx.x) >> 5;
    int lane = threadIdx.x & 31;
    if (warp >= NNODES) return;
    const float* h = g_out2 + (size_t)warp * HID;
    float acc = h[lane] * Wc[lane] + h[lane + 32] * Wc[lane + 32];
    #pragma unroll
    for (int o = 16; o; o >>= 1) acc += __shfl_xor_sync(0xFFFFFFFFu, acc, o);
    if (lane == 0) out[warp] = 1.f / (1.f + __expf(-(acc + bc[0])));
}

// ---------------- host launcher ----------------
extern "C" void kernel_launch(void* const* d_in, const int* in_sizes, int n_in,
                              void* d_out, int out_size) {
    const float* x      = (const float*)d_in[0];
    const int*   eidx   = (const int*)d_in[1];
    const float* W1l    = (const float*)d_in[2];
    const float* b1l    = (const float*)d_in[3];
    const float* W1r    = (const float*)d_in[4];
    const float* b1r    = (const float*)d_in[5];
    const float* att1   = (const float*)d_in[6];
    const float* bias1  = (const float*)d_in[7];
    const float* bn1_g  = (const float*)d_in[8];
    const float* bn1_b  = (const float*)d_in[9];
    const float* bn1_m  = (const float*)d_in[10];
    const float* bn1_v  = (const float*)d_in[11];
    const float* W2l    = (const float*)d_in[12];
    const float* b2l    = (const float*)d_in[13];
    const float* W2r    = (const float*)d_in[14];
    const float* b2r    = (const float*)d_in[15];
    const float* att2   = (const float*)d_in[16];
    const float* bias2  = (const float*)d_in[17];
    const float* bn2_g  = (const float*)d_in[18];
    const float* bn2_b  = (const float*)d_in[19];
    const float* bn2_m  = (const float*)d_in[20];
    const float* bn2_v  = (const float*)d_in[21];
    const float* Wc     = (const float*)d_in[22];
    const float* bc     = (const float*)d_in[23];
    float* out = (float*)d_out;

    const int n  = in_sizes[0] / IN_CH;    // 50000
    const int ne = in_sizes[1] / 2;        // 800000
    const int ee = ne + n;                 // 850000
    const int* esrc = eidx;
    const int* edst = eidx + ne;

    // init accumulators
    init_kernel<<<1024, 256>>>();

    // layer 1 transforms: xl1 = x@W1l+b1l, xr1 = x@W1r+b1r
    {
        dim3 grid((C1 + 63) / 64, (n + 63) / 64);
        sgemm_bias<<<grid, 256>>>(x, -1, W1l, b1l, /*cId=*/0, n, IN_CH, C1);
        sgemm_bias<<<grid, 256>>>(x, -1, W1r, b1r, /*cId=*/1, n, IN_CH, C1);
    }

    // layer 1 edge passes
    {
        int blocks = (ee * 32 + 255) / 256;
        gat1_logits<<<blocks, 256>>>(esrc, edst, ne, ee, att1);
        gat1_agg<<<blocks, 256>>>(esrc, edst, ne, ee);
    }
    finalize1<<<(NNODES * C1 + 255) / 256, 256>>>(bias1, bn1_g, bn1_b, bn1_m, bn1_v);

    // layer 2 transforms: xl2 = h1@W2l+b2l, xr2 = h1@W2r+b2r   (h1 lives in g_out1)
    {
        dim3 grid((HID + 63) / 64, (n + 63) / 64);
        sgemm_bias<<<grid, 256>>>(nullptr, /*aId=*/2, W2l, b2l, /*cId=*/3, n, C1, HID);
        sgemm_bias<<<grid, 256>>>(nullptr, /*aId=*/2, W2r, b2r, /*cId=*/4, n, C1, HID);
    }

    // layer 2 edge passes
    {
        int blocks = (ee * 32 + 255) / 256;
        gat2_logits<<<blocks, 256>>>(esrc, edst, ne, ee, att2);
        gat2_agg<<<blocks, 256>>>(esrc, edst, ne, ee);
    }
    finalize2<<<(NNODES * HID + 255) / 256, 256>>>(bias2, bn2_g, bn2_b, bn2_m, bn2_v);

    // classifier
    classifier<<<(NNODES * 32 + 255) / 256, 256>>>(Wc, bc, out);
}

// round 8
// speedup vs baseline: 1.5780x; 1.5780x over previous
#include <cuda_runtime.h>
#include <math.h>

// ---------------- problem constants (fixed shapes) ----------------
#define NNODES 50000
#define NEDGES 800000
#define IN_CH  256
#define HID    64
#define HEADS  2
#define C1     (HEADS * HID)        // 128
#define EE     (NEDGES + NNODES)    // 850000 edges incl. self loops
#define NEG_SLOPE 0.2f
#define BN_EPS    1e-5f

// ---------------- scratch (device globals; no allocations) ----------------
__device__ float g_xl1[NNODES * C1];
__device__ float g_xr1[NNODES * C1];
__device__ float g_h1 [NNODES * C1];
__device__ float g_xl2[NNODES * HID];
__device__ float g_xr2[NNODES * HID];
__device__ float g_h2 [NNODES * HID];
__device__ int   g_rowptr[NNODES + 1];
__device__ int   g_fill[NNODES];
__device__ int   g_eid[EE];

// ---------------- CSR build ----------------
__global__ void zero_rowptr() {
    int i = blockIdx.x * blockDim.x + threadIdx.x;
    if (i <= NNODES) g_rowptr[i] = 0;
}

__global__ void csr_hist(const int* __restrict__ edst, int ne, int ee) {
    int e = blockIdx.x * blockDim.x + threadIdx.x;
    if (e >= ee) return;
    int d = (e < ne) ? edst[e] : (e - ne);
    atomicAdd(&g_rowptr[d + 1], 1);
}

// single-block inclusive scan over NNODES+1 counts (rowptr[0]=0 preserved)
__global__ void csr_scan() {
    __shared__ int warpsums[32];
    __shared__ int carry;
    int tid = threadIdx.x;              // 1024 threads
    int lane = tid & 31, wid = tid >> 5;
    if (tid == 0) carry = 0;
    __syncthreads();
    for (int base = 0; base <= NNODES; base += 1024) {
        int idx = base + tid;
        int v = (idx <= NNODES) ? g_rowptr[idx] : 0;
        int x = v;
        #pragma unroll
        for (int o = 1; o < 32; o <<= 1) {
            int y = __shfl_up_sync(0xFFFFFFFFu, x, o);
            if (lane >= o) x += y;
        }
        if (lane == 31) warpsums[wid] = x;
        __syncthreads();
        if (wid == 0) {
            int w = warpsums[lane];
            #pragma unroll
            for (int o = 1; o < 32; o <<= 1) {
                int y = __shfl_up_sync(0xFFFFFFFFu, w, o);
                if (lane >= o) w += y;
            }
            warpsums[lane] = w;
        }
        __syncthreads();
        int incl = x + (wid > 0 ? warpsums[wid - 1] : 0) + carry;
        if (idx <= NNODES) g_rowptr[idx] = incl;
        __syncthreads();
        if (tid == 1023) carry = incl;
        __syncthreads();
    }
}

__global__ void csr_copy_fill() {
    int i = blockIdx.x * blockDim.x + threadIdx.x;
    if (i < NNODES) g_fill[i] = g_rowptr[i];
}

__global__ void csr_scatter(const int* __restrict__ esrc, const int* __restrict__ edst,
                            int ne, int ee) {
    int e = blockIdx.x * blockDim.x + threadIdx.x;
    if (e >= ee) return;
    int s, d;
    if (e < ne) { s = esrc[e]; d = edst[e]; }
    else        { s = e - ne; d = s; }
    int pos = atomicAdd(&g_fill[d], 1);
    g_eid[pos] = s;
}

// ---------------- tiled SGEMM with bias: C[M,N] = A[M,K]@B[K,N] + bias ----------------
__device__ __forceinline__ float* scr(int id) {
    switch (id) {
        case 0: return g_xl1;
        case 1: return g_xr1;
        case 2: return g_h1;
        case 3: return g_xl2;
        case 4: return g_xr2;
    }
    return nullptr;
}

__global__ void sgemm_bias(const float* __restrict__ Aext, int aId,
                           const float* __restrict__ B,
                           const float* __restrict__ bias,
                           int cId, int M, int K, int N) {
    const float* A = (aId >= 0) ? scr(aId) : Aext;
    float* C = scr(cId);

    __shared__ float As[16][64];   // [k][row]
    __shared__ float Bs[16][64];   // [k][col]

    int tid = threadIdx.x;                // 256 threads
    int tx = tid % 16, ty = tid / 16;     // 16x16 thread tile, each does 4x4
    int rowBase = blockIdx.y * 64;
    int colBase = blockIdx.x * 64;

    float acc[4][4] = {};
    for (int k0 = 0; k0 < K; k0 += 16) {
        #pragma unroll
        for (int i = 0; i < 4; i++) {
            int lin = tid + i * 256;          // 0..1023
            int r  = lin >> 4, kk = lin & 15; // A tile 64x16
            int grow = rowBase + r;
            As[kk][r] = (grow < M) ? A[(size_t)grow * K + k0 + kk] : 0.f;
            int kb = lin >> 6, cb = lin & 63; // B tile 16x64
            int gcol = colBase + cb;
            Bs[kb][cb] = (gcol < N) ? B[(size_t)(k0 + kb) * N + gcol] : 0.f;
        }
        __syncthreads();
        #pragma unroll
        for (int kk = 0; kk < 16; kk++) {
            float ra[4], rb[4];
            #pragma unroll
            for (int i = 0; i < 4; i++) ra[i] = As[kk][ty * 4 + i];
            #pragma unroll
            for (int j = 0; j < 4; j++) rb[j] = Bs[kk][tx * 4 + j];
            #pragma unroll
            for (int i = 0; i < 4; i++)
                #pragma unroll
                for (int j = 0; j < 4; j++) acc[i][j] += ra[i] * rb[j];
        }
        __syncthreads();
    }
    #pragma unroll
    for (int i = 0; i < 4; i++) {
        int grow = rowBase + ty * 4 + i;
        if (grow >= M) continue;
        #pragma unroll
        for (int j = 0; j < 4; j++) {
            int gcol = colBase + tx * 4 + j;
            if (gcol < N) C[(size_t)grow * N + gcol] = acc[i][j] + bias[gcol];
        }
    }
}

// ---------------- layer 1 fused: online softmax + aggregation + bias + BN + ELU ----
// one warp per destination node; lane covers channels [4*lane, 4*lane+4)
// lanes 0-15 -> head 0 (ch 0..63), lanes 16-31 -> head 1 (ch 64..127)
__global__ void gat1_fused(const float* __restrict__ att, const float* __restrict__ bias,
                           const float* __restrict__ bng, const float* __restrict__ bnb,
                           const float* __restrict__ bnm, const float* __restrict__ bnv) {
    int warp = (blockIdx.x * blockDim.x + threadIdx.x) >> 5;
    int lane = threadIdx.x & 31;
    if (warp >= NNODES) return;
    int d = warp;
    int cbase = lane * 4;

    float4 xr = *(const float4*)(g_xr1 + (size_t)d * C1 + cbase);
    float4 a4 = *(const float4*)(att + cbase);

    float4 acc = make_float4(0.f, 0.f, 0.f, 0.f);
    float m = -INFINITY, s = 0.f;

    int start = g_rowptr[d], end = g_rowptr[d + 1];
    for (int base = start; base < end; base += 32) {
        int sv = (base + lane < end) ? g_eid[base + lane] : 0;
        int nb = min(32, end - base);
        for (int j = 0; j < nb; j++) {
            int src = __shfl_sync(0xFFFFFFFFu, sv, j);
            float4 xl = *(const float4*)(g_xl1 + (size_t)src * C1 + cbase);
            float v0 = xl.x + xr.x; v0 = v0 > 0.f ? v0 : NEG_SLOPE * v0;
            float v1 = xl.y + xr.y; v1 = v1 > 0.f ? v1 : NEG_SLOPE * v1;
            float v2 = xl.z + xr.z; v2 = v2 > 0.f ? v2 : NEG_SLOPE * v2;
            float v3 = xl.w + xr.w; v3 = v3 > 0.f ? v3 : NEG_SLOPE * v3;
            float t = a4.x * v0 + a4.y * v1 + a4.z * v2 + a4.w * v3;
            // butterfly reduce within each 16-lane half (per-head logit)
            t += __shfl_xor_sync(0xFFFFFFFFu, t, 8);
            t += __shfl_xor_sync(0xFFFFFFFFu, t, 4);
            t += __shfl_xor_sync(0xFFFFFFFFu, t, 2);
            t += __shfl_xor_sync(0xFFFFFFFFu, t, 1);
            // online softmax update (per-head state, uniform within half-warp)
            float mn = fmaxf(m, t);
            float sc = __expf(m - mn);   // 0 on first edge (m = -inf)
            float p  = __expf(t - mn);
            s = s * sc + p;
            acc.x = acc.x * sc + p * xl.x;
            acc.y = acc.y * sc + p * xl.y;
            acc.z = acc.z * sc + p * xl.z;
            acc.w = acc.w * sc + p * xl.w;
            m = mn;
        }
    }

    float inv = 1.f / s;
    float4 bi = *(const float4*)(bias + cbase);
    float4 gg = *(const float4*)(bng + cbase);
    float4 bb = *(const float4*)(bnb + cbase);
    float4 mm = *(const float4*)(bnm + cbase);
    float4 vv = *(const float4*)(bnv + cbase);
    float4 o;
    o.x = (acc.x * inv + bi.x - mm.x) * rsqrtf(vv.x + BN_EPS) * gg.x + bb.x;
    o.y = (acc.y * inv + bi.y - mm.y) * rsqrtf(vv.y + BN_EPS) * gg.y + bb.y;
    o.z = (acc.z * inv + bi.z - mm.z) * rsqrtf(vv.z + BN_EPS) * gg.z + bb.z;
    o.w = (acc.w * inv + bi.w - mm.w) * rsqrtf(vv.w + BN_EPS) * gg.w + bb.w;
    o.x = o.x > 0.f ? o.x : __expf(o.x) - 1.f;
    o.y = o.y > 0.f ? o.y : __expf(o.y) - 1.f;
    o.z = o.z > 0.f ? o.z : __expf(o.z) - 1.f;
    o.w = o.w > 0.f ? o.w : __expf(o.w) - 1.f;
    *(float4*)(g_h1 + (size_t)d * C1 + cbase) = o;
}

// ---------------- layer 2 fused: 64 ch, 1 head; lane covers 2 channels ----------------
__global__ void gat2_fused(const float* __restrict__ att, const float* __restrict__ bias,
                           const float* __restrict__ bng, const float* __restrict__ bnb,
                           const float* __restrict__ bnm, const float* __restrict__ bnv) {
    int warp = (blockIdx.x * blockDim.x + threadIdx.x) >> 5;
    int lane = threadIdx.x & 31;
    if (warp >= NNODES) return;
    int d = warp;
    int cbase = lane * 2;

    float2 xr = *(const float2*)(g_xr2 + (size_t)d * HID + cbase);
    float2 a2 = *(const float2*)(att + cbase);

    float2 acc = make_float2(0.f, 0.f);
    float m = -INFINITY, s = 0.f;

    int start = g_rowptr[d], end = g_rowptr[d + 1];
    for (int base = start; base < end; base += 32) {
        int sv = (base + lane < end) ? g_eid[base + lane] : 0;
        int nb = min(32, end - base);
        for (int j = 0; j < nb; j++) {
            int src = __shfl_sync(0xFFFFFFFFu, sv, j);
            float2 xl = *(const float2*)(g_xl2 + (size_t)src * HID + cbase);
            float v0 = xl.x + xr.x; v0 = v0 > 0.f ? v0 : NEG_SLOPE * v0;
            float v1 = xl.y + xr.y; v1 = v1 > 0.f ? v1 : NEG_SLOPE * v1;
            float t = a2.x * v0 + a2.y * v1;
            #pragma unroll
            for (int o = 16; o; o >>= 1) t += __shfl_xor_sync(0xFFFFFFFFu, t, o);
            float mn = fmaxf(m, t);
            float sc = __expf(m - mn);
            float p  = __expf(t - mn);
            s = s * sc + p;
            acc.x = acc.x * sc + p * xl.x;
            acc.y = acc.y * sc + p * xl.y;
            m = mn;
        }
    }

    float inv = 1.f / s;
    float2 bi = *(const float2*)(bias + cbase);
    float2 gg = *(const float2*)(bng + cbase);
    float2 bb = *(const float2*)(bnb + cbase);
    float2 mm = *(const float2*)(bnm + cbase);
    float2 vv = *(const float2*)(bnv + cbase);
    float2 o;
    o.x = (acc.x * inv + bi.x - mm.x) * rsqrtf(vv.x + BN_EPS) * gg.x + bb.x;
    o.y = (acc.y * inv + bi.y - mm.y) * rsqrtf(vv.y + BN_EPS) * gg.y + bb.y;
    o.x = o.x > 0.f ? o.x : __expf(o.x) - 1.f;
    o.y = o.y > 0.f ? o.y : __expf(o.y) - 1.f;
    *(float2*)(g_h2 + (size_t)d * HID + cbase) = o;
}

// ---------------- classifier: sigmoid(h2 @ Wc + bc), warp per node ----------------
__global__ void classifier(const float* __restrict__ Wc, const float* __restrict__ bc,
                           float* __restrict__ out) {
    int warp = (blockIdx.x * blockDim.x + threadIdx.x) >> 5;
    int lane = threadIdx.x & 31;
    if (warp >= NNODES) return;
    const float* h = g_h2 + (size_t)warp * HID;
    float acc = h[lane] * Wc[lane] + h[lane + 32] * Wc[lane + 32];
    #pragma unroll
    for (int o = 16; o; o >>= 1) acc += __shfl_xor_sync(0xFFFFFFFFu, acc, o);
    if (lane == 0) out[warp] = 1.f / (1.f + __expf(-(acc + bc[0])));
}

// ---------------- host launcher ----------------
extern "C" void kernel_launch(void* const* d_in, const int* in_sizes, int n_in,
                              void* d_out, int out_size) {
    const float* x      = (const float*)d_in[0];
    const int*   eidx   = (const int*)d_in[1];
    const float* W1l    = (const float*)d_in[2];
    const float* b1l    = (const float*)d_in[3];
    const float* W1r    = (const float*)d_in[4];
    const float* b1r    = (const float*)d_in[5];
    const float* att1   = (const float*)d_in[6];
    const float* bias1  = (const float*)d_in[7];
    const float* bn1_g  = (const float*)d_in[8];
    const float* bn1_b  = (const float*)d_in[9];
    const float* bn1_m  = (const float*)d_in[10];
    const float* bn1_v  = (const float*)d_in[11];
    const float* W2l    = (const float*)d_in[12];
    const float* b2l    = (const float*)d_in[13];
    const float* W2r    = (const float*)d_in[14];
    const float* b2r    = (const float*)d_in[15];
    const float* att2   = (const float*)d_in[16];
    const float* bias2  = (const float*)d_in[17];
    const float* bn2_g  = (const float*)d_in[18];
    const float* bn2_b  = (const float*)d_in[19];
    const float* bn2_m  = (const float*)d_in[20];
    const float* bn2_v  = (const float*)d_in[21];
    const float* Wc     = (const float*)d_in[22];
    const float* bc     = (const float*)d_in[23];
    float* out = (float*)d_out;

    const int n  = in_sizes[0] / IN_CH;    // 50000
    const int ne = in_sizes[1] / 2;        // 800000
    const int ee = ne + n;                 // 850000
    const int* esrc = eidx;
    const int* edst = eidx + ne;

    // ---- CSR build (by destination) ----
    zero_rowptr<<<(NNODES + 256) / 256, 256>>>();
    csr_hist<<<(ee + 255) / 256, 256>>>(edst, ne, ee);
    csr_scan<<<1, 1024>>>();
    csr_copy_fill<<<(NNODES + 255) / 256, 256>>>();
    csr_scatter<<<(ee + 255) / 256, 256>>>(esrc, edst, ne, ee);

    // ---- layer 1 transforms ----
    {
        dim3 grid((C1 + 63) / 64, (n + 63) / 64);
        sgemm_bias<<<grid, 256>>>(x, -1, W1l, b1l, /*cId=*/0, n, IN_CH, C1);
        sgemm_bias<<<grid, 256>>>(x, -1, W1r, b1r, /*cId=*/1, n, IN_CH, C1);
    }

    // ---- layer 1 fused edge pass (softmax+agg+bias+BN+ELU) ----
    gat1_fused<<<(NNODES * 32 + 255) / 256, 256>>>(att1, bias1, bn1_g, bn1_b, bn1_m, bn1_v);

    // ---- layer 2 transforms (read g_h1) ----
    {
        dim3 grid((HID + 63) / 64, (n + 63) / 64);
        sgemm_bias<<<grid, 256>>>(nullptr, /*aId=*/2, W2l, b2l, /*cId=*/3, n, C1, HID);
        sgemm_bias<<<grid, 256>>>(nullptr, /*aId=*/2, W2r, b2r, /*cId=*/4, n, C1, HID);
    }

    // ---- layer 2 fused edge pass ----
    gat2_fused<<<(NNODES * 32 + 255) / 256, 256>>>(att2, bias2, bn2_g, bn2_b, bn2_m, bn2_v);

    // ---- classifier ----
    classifier<<<(NNODES * 32 + 255) / 256, 256>>>(Wc, bc, out);
}